// round 9
// baseline (speedup 1.0000x reference)
#include <cuda_runtime.h>

// Problem constants
#define BB 128
#define TT 2048
#define LL 8              // timesteps per chunk
#define CC (TT / LL)      // 256 chunks per batch
#define NM (BB * TT)      // 262144 matrices total
#define DT 0.02f

// Scratch: 32 floats per 4x4 complex matrix = [re[16], im[16]] = 8 float4 (128B)
__device__ __align__(128) float4 g_U[(size_t)NM * 8];        // 33.5 MB: all unitaries
__device__ __align__(128) float4 g_P[(size_t)BB * CC * 8];   // chunk products
__device__ __align__(128) float4 g_S[(size_t)BB * CC * 8];   // incoming state per chunk

// ---------------------------------------------------------------------------
// Packed f32x2 primitives (FFMA2 — only reachable via PTX)
typedef unsigned long long u64p;

__device__ __forceinline__ u64p pk2(float x, float y) {
    u64p r; asm("mov.b64 %0, {%1, %2};" : "=l"(r) : "f"(x), "f"(y)); return r;
}
__device__ __forceinline__ void upk2(u64p v, float& x, float& y) {
    asm("mov.b64 {%0, %1}, %2;" : "=f"(x), "=f"(y) : "l"(v));
}
__device__ __forceinline__ u64p psplat(float a) { return pk2(a, a); }
__device__ __forceinline__ u64p pfma(u64p a, u64p b, u64p c) {
    u64p r; asm("fma.rn.f32x2 %0, %1, %2, %3;" : "=l"(r) : "l"(a), "l"(b), "l"(c)); return r;
}
__device__ __forceinline__ u64p pmul(u64p a, u64p b) {
    u64p r; asm("mul.rn.f32x2 %0, %1, %2;" : "=l"(r) : "l"(a), "l"(b)); return r;
}
__device__ __forceinline__ u64p padd(u64p a, u64p b) {
    u64p r; asm("add.rn.f32x2 %0, %1, %2;" : "=l"(r) : "l"(a), "l"(b)); return r;
}

struct PRow { u64p r01, r23, i01, i23; };

__device__ __forceinline__ void caccum(float a, float b, const PRow& y, PRow& z) {
    u64p sa = psplat(a), sb = psplat(b), snb = psplat(-b);
    z.r01 = pfma(sa, y.r01, pfma(snb, y.i01, z.r01));
    z.r23 = pfma(sa, y.r23, pfma(snb, y.i23, z.r23));
    z.i01 = pfma(sa, y.i01, pfma(sb, y.r01, z.i01));
    z.i23 = pfma(sa, y.i23, pfma(sb, y.r23, z.i23));
}

// z_row = x_row * Y  (one output row; zero-init inside)
__device__ __forceinline__ PRow prow_mm(const PRow& xrow, const PRow* __restrict__ y) {
    PRow z; z.r01 = pk2(0, 0); z.r23 = pk2(0, 0); z.i01 = pk2(0, 0); z.i23 = pk2(0, 0);
    float e0, e1, e2, e3, f0, f1, f2, f3;
    upk2(xrow.r01, e0, e1); upk2(xrow.r23, e2, e3);
    upk2(xrow.i01, f0, f1); upk2(xrow.i23, f2, f3);
    caccum(e0, f0, y[0], z);
    caccum(e1, f1, y[1], z);
    caccum(e2, f2, y[2], z);
    caccum(e3, f3, y[3], z);
    return z;
}

// ---------------------------------------------------------------------------
// Scalar helpers
__device__ __forceinline__ void cax4(float a, float b, float4 cr, float4 ci,
                                     float4& accr, float4& acci) {
    accr.x = fmaf(a, cr.x, fmaf(-b, ci.x, accr.x));
    acci.x = fmaf(a, ci.x, fmaf( b, cr.x, acci.x));
    accr.y = fmaf(a, cr.y, fmaf(-b, ci.y, accr.y));
    acci.y = fmaf(a, ci.y, fmaf( b, cr.y, acci.y));
    accr.z = fmaf(a, cr.z, fmaf(-b, ci.z, accr.z));
    acci.z = fmaf(a, ci.z, fmaf( b, cr.z, acci.z));
    accr.w = fmaf(a, cr.w, fmaf(-b, ci.w, accr.w));
    acci.w = fmaf(a, ci.w, fmaf( b, cr.w, acci.w));
}

// shuffle one full float4-pair row from lane `src` (every lane passes its own row)
__device__ __forceinline__ void shfl_row(float4 pr, float4 pim, int src,
                                         float4& outr, float4& outi) {
    outr.x = __shfl_sync(0xffffffffu, pr.x, src);
    outr.y = __shfl_sync(0xffffffffu, pr.y, src);
    outr.z = __shfl_sync(0xffffffffu, pr.z, src);
    outr.w = __shfl_sync(0xffffffffu, pr.w, src);
    outi.x = __shfl_sync(0xffffffffu, pim.x, src);
    outi.y = __shfl_sync(0xffffffffu, pim.y, src);
    outi.z = __shfl_sync(0xffffffffu, pim.z, src);
    outi.w = __shfl_sync(0xffffffffu, pim.w, src);
}

// ---------------------------------------------------------------------------
// K0: U = expm(-i*dt*H), degree-4 Taylor via packed f32x2, register-lean:
//   B = A^2;  E = A + M·B  with M = I/2 + A/6 + B/24 built ROW-WISE (A,B
//   commute, so M·B == B·M).  Then fused chunk product via a 3-round
//   shfl_xor tree with IN-PLACE row-wise matmuls. No smem, no barriers.
__global__ void __launch_bounds__(128, 6) k_expm(const float* __restrict__ hr_g,
                                                 const float* __restrict__ hi_g) {
    int tid = threadIdx.x;
    int idx = blockIdx.x * 128 + tid;

    const float4* hr4 = reinterpret_cast<const float4*>(hr_g) + (size_t)idx * 4;
    const float4* hi4 = reinterpret_cast<const float4*>(hi_g) + (size_t)idx * 4;

    // A = dt*hi - i*dt*hr
    PRow A[4];
    const u64p pdt = psplat(DT), pndt = psplat(-DT);
#pragma unroll
    for (int i = 0; i < 4; ++i) {
        float4 r = hr4[i], m = hi4[i];
        A[i].r01 = pmul(pdt,  pk2(m.x, m.y));
        A[i].r23 = pmul(pdt,  pk2(m.z, m.w));
        A[i].i01 = pmul(pndt, pk2(r.x, r.y));
        A[i].i23 = pmul(pndt, pk2(r.z, r.w));
    }

    // B = A^2 (row-wise outputs, y=A fully live)
    PRow B[4];
#pragma unroll
    for (int i = 0; i < 4; ++i) B[i] = prow_mm(A[i], A);

    // E = A + M·B, building M row-by-row:  m_i = I/2|row_i + A_i/6 + B_i/24
    const u64p c6 = psplat(1.0f / 6.0f), c24 = psplat(1.0f / 24.0f);
#pragma unroll
    for (int i = 0; i < 4; ++i) {
        PRow m;
        m.r01 = pfma(c6, A[i].r01, pmul(c24, B[i].r01));
        m.r23 = pfma(c6, A[i].r23, pmul(c24, B[i].r23));
        m.i01 = pfma(c6, A[i].i01, pmul(c24, B[i].i01));
        m.i23 = pfma(c6, A[i].i23, pmul(c24, B[i].i23));
        // + I/2 on the diagonal of row i
        if (i == 0) m.r01 = padd(m.r01, pk2(0.5f, 0.0f));
        if (i == 1) m.r01 = padd(m.r01, pk2(0.0f, 0.5f));
        if (i == 2) m.r23 = padd(m.r23, pk2(0.5f, 0.0f));
        if (i == 3) m.r23 = padd(m.r23, pk2(0.0f, 0.5f));
        // A_i += m · B   (accumulate into A row)
        float e0, e1, e2, e3, f0, f1, f2, f3;
        upk2(m.r01, e0, e1); upk2(m.r23, e2, e3);
        upk2(m.i01, f0, f1); upk2(m.i23, f2, f3);
        caccum(e0, f0, B[0], A[i]);
        caccum(e1, f1, B[1], A[i]);
        caccum(e2, f2, B[2], A[i]);
        caccum(e3, f3, B[3], A[i]);
    }
    A[0].r01 = padd(A[0].r01, pk2(1.0f, 0.0f));
    A[1].r01 = padd(A[1].r01, pk2(0.0f, 1.0f));
    A[2].r23 = padd(A[2].r23, pk2(1.0f, 0.0f));
    A[3].r23 = padd(A[3].r23, pk2(0.0f, 1.0f));

    // store U to global (planar: re[16] then im[16])
    {
        float4* Up = g_U + (size_t)idx * 8;
#pragma unroll
        for (int i = 0; i < 4; ++i) {
            float x0, x1, x2, x3;
            upk2(A[i].r01, x0, x1); upk2(A[i].r23, x2, x3);
            Up[i] = make_float4(x0, x1, x2, x3);
        }
#pragma unroll
        for (int i = 0; i < 4; ++i) {
            float x0, x1, x2, x3;
            upk2(A[i].i01, x0, x1); upk2(A[i].i23, x2, x3);
            Up[4 + i] = make_float4(x0, x1, x2, x3);
        }
    }

    // ---- chunk product: shfl_xor tree over the 8 lanes holding U_0..U_7.
    // After round d every lane holds the ordered product of its 2d-block.
#pragma unroll
    for (int d = 1; d < 8; d <<= 1) {
        PRow Q[4];
#pragma unroll
        for (int i = 0; i < 4; ++i) {
            Q[i].r01 = __shfl_xor_sync(0xffffffffu, A[i].r01, d);
            Q[i].r23 = __shfl_xor_sync(0xffffffffu, A[i].r23, d);
            Q[i].i01 = __shfl_xor_sync(0xffffffffu, A[i].i01, d);
            Q[i].i23 = __shfl_xor_sync(0xffffffffu, A[i].i23, d);
        }
        bool hi = (tid & d) != 0;
        // conditional swap so result is always A_new = A * Q = higher * lower
#pragma unroll
        for (int i = 0; i < 4; ++i) {
            u64p a, b;
            a = A[i].r01; b = Q[i].r01; A[i].r01 = hi ? a : b; Q[i].r01 = hi ? b : a;
            a = A[i].r23; b = Q[i].r23; A[i].r23 = hi ? a : b; Q[i].r23 = hi ? b : a;
            a = A[i].i01; b = Q[i].i01; A[i].i01 = hi ? a : b; Q[i].i01 = hi ? b : a;
            a = A[i].i23; b = Q[i].i23; A[i].i23 = hi ? a : b; Q[i].i23 = hi ? b : a;
        }
        // in-place row-wise: A_i only feeds row i of the product
#pragma unroll
        for (int i = 0; i < 4; ++i) A[i] = prow_mm(A[i], Q);
    }

    // every lane of the 8-group holds the full product; lane g stores quad g
    // (quads 0-3 = real rows, 4-7 = imag rows) -> warp writes 512B contiguous.
    {
        int g = tid & 7;
        bool gi = (g & 4) != 0;
        u64p s0 = gi ? A[0].i01 : A[0].r01;
        u64p s1 = gi ? A[1].i01 : A[1].r01;
        u64p s2 = gi ? A[2].i01 : A[2].r01;
        u64p s3 = gi ? A[3].i01 : A[3].r01;
        u64p t0 = gi ? A[0].i23 : A[0].r23;
        u64p t1 = gi ? A[1].i23 : A[1].r23;
        u64p t2 = gi ? A[2].i23 : A[2].r23;
        u64p t3 = gi ? A[3].i23 : A[3].r23;
        u64p lo = (g & 2) ? ((g & 1) ? s3 : s2) : ((g & 1) ? s1 : s0);
        u64p hi2 = (g & 2) ? ((g & 1) ? t3 : t2) : ((g & 1) ? t1 : t0);
        float x0, x1, x2, x3;
        upk2(lo, x0, x1); upk2(hi2, x2, x3);
        int chunk = idx >> 3;
        g_P[(size_t)chunk * 8 + g] = make_float4(x0, x1, x2, x3);
    }
}

// ---------------------------------------------------------------------------
// K2: TWO-LEVEL row-parallel scan per batch. 1024 threads = 256 chunks x 4 rows.
#define TOFF 288   // T_B offset (T matrices stride 9 quads; 32*9=288 per buffer)

__global__ void __launch_bounds__(1024) k_scan(const float* __restrict__ s0r_g,
                                               const float* __restrict__ s0i_g) {
    __shared__ float4 sh[CC * 12];   // 48KB; quads [0,576) double as T_A/T_B
    int b = blockIdx.x;
    int tid = threadIdx.x;
    int e = tid >> 2, i = tid & 3;
    int lane = tid & 31;
    int el = lane >> 2;              // local chunk within warp (0..7)
    int g = e >> 3;                  // group (= warp id, 0..31)

    const float4* Pg = g_P + ((size_t)b * CC + e) * 8;
    float4 pr = Pg[i], pim = Pg[4 + i];

    // ---- L1: warp-local KS over 8 (rows fetched via shfl)
#pragma unroll
    for (int d = 1; d < 8; d <<= 1) {
        int srcb = ((el >= d) ? (el - d) : 0) << 2;
        float4 l0r, l0i, l1r, l1i, l2r, l2i, l3r, l3i;
        shfl_row(pr, pim, srcb + 0, l0r, l0i);
        shfl_row(pr, pim, srcb + 1, l1r, l1i);
        shfl_row(pr, pim, srcb + 2, l2r, l2i);
        shfl_row(pr, pim, srcb + 3, l3r, l3i);
        if (el >= d) {
            float4 nr = make_float4(0, 0, 0, 0), ni = make_float4(0, 0, 0, 0);
            cax4(pr.x, pim.x, l0r, l0i, nr, ni);
            cax4(pr.y, pim.y, l1r, l1i, nr, ni);
            cax4(pr.z, pim.z, l2r, l2i, nr, ni);
            cax4(pr.w, pim.w, l3r, l3i, nr, ni);
            pr = nr; pim = ni;
        }
    }

    // ---- publish group totals (el==7) into T_A (stride 9 quads per matrix)
    if (el == 7) {
        sh[g * 9 + i] = pr;
        sh[g * 9 + 4 + i] = pim;
    }
    __syncthreads();

    // ---- L2: KS over 32 totals, 128 threads, 5 rounds, double-buffered
    if (tid < 128) {
        int g2 = tid >> 2, i2 = tid & 3;
        int rb = 0;
#pragma unroll
        for (int d = 1; d < 32; d <<= 1) {
            const float4* src = sh + rb;
            float4* dst = sh + (TOFF - rb);
            float4 qr = src[g2 * 9 + i2], qi = src[g2 * 9 + 4 + i2];
            if (g2 >= d) {
                const float4* nb = src + (size_t)(g2 - d) * 9;
                float4 nr = make_float4(0, 0, 0, 0), ni = make_float4(0, 0, 0, 0);
                cax4(qr.x, qi.x, nb[0], nb[4], nr, ni);
                cax4(qr.y, qi.y, nb[1], nb[5], nr, ni);
                cax4(qr.z, qi.z, nb[2], nb[6], nr, ni);
                cax4(qr.w, qi.w, nb[3], nb[7], nr, ni);
                qr = nr; qi = ni;
            }
            dst[g2 * 9 + i2] = qr;
            dst[g2 * 9 + 4 + i2] = qi;
            asm volatile("bar.sync 1, 128;" ::: "memory");
            rb = TOFF - rb;
        }
    }
    __syncthreads();
    // G (inclusive group prefixes) now at sh + TOFF

    // ---- inclusive prefix: Q_e * G_{g-1}
    if (g > 0) {
        const float4* nb = sh + TOFF + (size_t)(g - 1) * 9;
        float4 nr = make_float4(0, 0, 0, 0), ni = make_float4(0, 0, 0, 0);
        cax4(pr.x, pim.x, nb[0], nb[4], nr, ni);
        cax4(pr.y, pim.y, nb[1], nb[5], nr, ni);
        cax4(pr.z, pim.z, nb[2], nb[6], nr, ni);
        cax4(pr.w, pim.w, nb[3], nb[7], nr, ni);
        pr = nr; pim = ni;
    }
    __syncthreads();   // everyone done reading T before overwriting sh below

    // ---- publish inclusive rows (XOR-swizzled layout)
    int es = e & 7;
    {
        float4* me = sh + e * 12;
        me[i ^ es] = pr;
        me[(4 + i) ^ es] = pim;
    }
    __syncthreads();

    // ---- V_e = Prefix_{e-1} * S0  (V_0 = S0)
    const float4* r4 = reinterpret_cast<const float4*>(s0r_g) + (size_t)b * 4;
    const float4* i4 = reinterpret_cast<const float4*>(s0i_g) + (size_t)b * 4;
    float4 s0r0 = r4[0], s0r1 = r4[1], s0r2 = r4[2], s0r3 = r4[3];
    float4 s0i0 = i4[0], s0i1 = i4[1], s0i2 = i4[2], s0i3 = i4[3];

    float4 vr, vi;
    if (e == 0) {
        vr = (i == 0) ? s0r0 : (i == 1) ? s0r1 : (i == 2) ? s0r2 : s0r3;
        vi = (i == 0) ? s0i0 : (i == 1) ? s0i1 : (i == 2) ? s0i2 : s0i3;
    } else {
        int ens = (e - 1) & 7;
        const float4* nb = sh + (e - 1) * 12;
        float4 qr = nb[i ^ ens];
        float4 qi = nb[(4 + i) ^ ens];
        vr = make_float4(0, 0, 0, 0); vi = make_float4(0, 0, 0, 0);
        cax4(qr.x, qi.x, s0r0, s0i0, vr, vi);
        cax4(qr.y, qi.y, s0r1, s0i1, vr, vi);
        cax4(qr.z, qi.z, s0r2, s0i2, vr, vi);
        cax4(qr.w, qi.w, s0r3, s0i3, vr, vi);
    }
    float4* Sg = g_S + ((size_t)b * CC + e) * 8;
    Sg[i] = vr;
    Sg[4 + i] = vi;
}

// ---------------------------------------------------------------------------
// K3: ROW-parallel apply, BATCH-MAJOR mapping: warp's 8 chunk-groups are 8
// consecutive b with the same c -> each STG.128 is part of a 512B-contiguous
// warp store. State in smem double-buffered, stride 13 (conflict-free).
#define SSTR 13

__global__ void __launch_bounds__(128) k_apply(float* __restrict__ out) {
    __shared__ float4 sS[2][32 * SSTR];      // 13,312 B

    int tid = threadIdx.x;
    int cl = tid >> 2, i = tid & 3;
    int gidx = blockIdx.x * 32 + cl;         // b-fast ordering
    int b = gidx & (BB - 1);
    int c = gidx >> 7;                       // / BB
    int idx = b * CC + c;                    // chunk index in g_U/g_S

    {   // stage incoming state rows
        const float4* Sg = g_S + (size_t)idx * 8;
        sS[0][cl * SSTR + i] = Sg[i];
        sS[0][cl * SSTR + 4 + i] = Sg[4 + i];
    }

    const float4* Ug = g_U + (size_t)idx * 64;
    float4 ur = Ug[i], ui = Ug[4 + i];       // prefetch l=0

    __syncwarp();

    const size_t imag_off = (size_t)TT * BB * 16;
    float* ob = out + (((size_t)c * LL) * BB + b) * 16 + i * 4;

#pragma unroll
    for (int l = 0; l < LL; ++l) {
        float4 nur, nui;
        if (l < LL - 1) {
            nur = Ug[(l + 1) * 8 + i];
            nui = Ug[(l + 1) * 8 + 4 + i];
        }

        const int cur = l & 1;
        float4 s0r = sS[cur][cl * SSTR + 0];
        float4 s1r = sS[cur][cl * SSTR + 1];
        float4 s2r = sS[cur][cl * SSTR + 2];
        float4 s3r = sS[cur][cl * SSTR + 3];
        float4 s0i = sS[cur][cl * SSTR + 4];
        float4 s1i = sS[cur][cl * SSTR + 5];
        float4 s2i = sS[cur][cl * SSTR + 6];
        float4 s3i = sS[cur][cl * SSTR + 7];

        float4 nr = make_float4(0, 0, 0, 0), ni = make_float4(0, 0, 0, 0);
        cax4(ur.x, ui.x, s0r, s0i, nr, ni);
        cax4(ur.y, ui.y, s1r, s1i, nr, ni);
        cax4(ur.z, ui.z, s2r, s2i, nr, ni);
        cax4(ur.w, ui.w, s3r, s3i, nr, ni);

        if (l < LL - 1) {
            sS[cur ^ 1][cl * SSTR + i] = nr;
            sS[cur ^ 1][cl * SSTR + 4 + i] = ni;
        }

        float* op = ob + (size_t)l * BB * 16;
        __stcs(reinterpret_cast<float4*>(op), nr);
        __stcs(reinterpret_cast<float4*>(op + imag_off), ni);

        __syncwarp();
        ur = nur; ui = nui;
    }
}

// ---------------------------------------------------------------------------
extern "C" void kernel_launch(void* const* d_in, const int* in_sizes, int n_in,
                              void* d_out, int out_size) {
    const float* h_real = (const float*)d_in[0];
    const float* h_imag = (const float*)d_in[1];
    const float* s_real = (const float*)d_in[2];
    const float* s_imag = (const float*)d_in[3];
    float* out = (float*)d_out;

    k_expm<<<NM / 128, 128>>>(h_real, h_imag);
    k_scan<<<BB, CC * 4>>>(s_real, s_imag);
    k_apply<<<(BB * CC) / 32, 128>>>(out);
}

// round 10
// speedup vs baseline: 1.0485x; 1.0485x over previous
#include <cuda_runtime.h>

// Problem constants
#define BB 128
#define TT 2048
#define LL 8              // timesteps per chunk
#define CC (TT / LL)      // 256 chunks per batch
#define NM (BB * TT)      // 262144 matrices total
#define DT 0.02f

// Scratch: 32 floats per 4x4 complex matrix = [re[16], im[16]] = 8 float4 (128B)
// g_U now holds intra-chunk PREFIX products: entry (b, c*8+l) = U_l...U_0 of chunk c.
__device__ __align__(128) float4 g_U[(size_t)NM * 8];        // 33.5 MB
__device__ __align__(128) float4 g_S[(size_t)BB * CC * 8];   // incoming state per chunk

// ---------------------------------------------------------------------------
// Packed f32x2 primitives (FFMA2 — only reachable via PTX)
typedef unsigned long long u64p;

__device__ __forceinline__ u64p pk2(float x, float y) {
    u64p r; asm("mov.b64 %0, {%1, %2};" : "=l"(r) : "f"(x), "f"(y)); return r;
}
__device__ __forceinline__ void upk2(u64p v, float& x, float& y) {
    asm("mov.b64 {%0, %1}, %2;" : "=f"(x), "=f"(y) : "l"(v));
}
__device__ __forceinline__ u64p psplat(float a) { return pk2(a, a); }
__device__ __forceinline__ u64p pfma(u64p a, u64p b, u64p c) {
    u64p r; asm("fma.rn.f32x2 %0, %1, %2, %3;" : "=l"(r) : "l"(a), "l"(b), "l"(c)); return r;
}
__device__ __forceinline__ u64p pmul(u64p a, u64p b) {
    u64p r; asm("mul.rn.f32x2 %0, %1, %2;" : "=l"(r) : "l"(a), "l"(b)); return r;
}
__device__ __forceinline__ u64p padd(u64p a, u64p b) {
    u64p r; asm("add.rn.f32x2 %0, %1, %2;" : "=l"(r) : "l"(a), "l"(b)); return r;
}

struct PRow { u64p r01, r23, i01, i23; };

__device__ __forceinline__ void caccum(float a, float b, const PRow& y, PRow& z) {
    u64p sa = psplat(a), sb = psplat(b), snb = psplat(-b);
    z.r01 = pfma(sa, y.r01, pfma(snb, y.i01, z.r01));
    z.r23 = pfma(sa, y.r23, pfma(snb, y.i23, z.r23));
    z.i01 = pfma(sa, y.i01, pfma(sb, y.r01, z.i01));
    z.i23 = pfma(sa, y.i23, pfma(sb, y.r23, z.i23));
}

// z_row = x_row * Y  (one output row; zero-init inside)
__device__ __forceinline__ PRow prow_mm(const PRow& xrow, const PRow* __restrict__ y) {
    PRow z; z.r01 = pk2(0, 0); z.r23 = pk2(0, 0); z.i01 = pk2(0, 0); z.i23 = pk2(0, 0);
    float e0, e1, e2, e3, f0, f1, f2, f3;
    upk2(xrow.r01, e0, e1); upk2(xrow.r23, e2, e3);
    upk2(xrow.i01, f0, f1); upk2(xrow.i23, f2, f3);
    caccum(e0, f0, y[0], z);
    caccum(e1, f1, y[1], z);
    caccum(e2, f2, y[2], z);
    caccum(e3, f3, y[3], z);
    return z;
}

// ---------------------------------------------------------------------------
// Scalar helpers
__device__ __forceinline__ void cax4(float a, float b, float4 cr, float4 ci,
                                     float4& accr, float4& acci) {
    accr.x = fmaf(a, cr.x, fmaf(-b, ci.x, accr.x));
    acci.x = fmaf(a, ci.x, fmaf( b, cr.x, acci.x));
    accr.y = fmaf(a, cr.y, fmaf(-b, ci.y, accr.y));
    acci.y = fmaf(a, ci.y, fmaf( b, cr.y, acci.y));
    accr.z = fmaf(a, cr.z, fmaf(-b, ci.z, accr.z));
    acci.z = fmaf(a, ci.z, fmaf( b, cr.z, acci.z));
    accr.w = fmaf(a, cr.w, fmaf(-b, ci.w, accr.w));
    acci.w = fmaf(a, ci.w, fmaf( b, cr.w, acci.w));
}

// shuffle one full float4-pair row from lane `src`
__device__ __forceinline__ void shfl_row(float4 pr, float4 pim, int src,
                                         float4& outr, float4& outi) {
    outr.x = __shfl_sync(0xffffffffu, pr.x, src);
    outr.y = __shfl_sync(0xffffffffu, pr.y, src);
    outr.z = __shfl_sync(0xffffffffu, pr.z, src);
    outr.w = __shfl_sync(0xffffffffu, pr.w, src);
    outi.x = __shfl_sync(0xffffffffu, pim.x, src);
    outi.y = __shfl_sync(0xffffffffu, pim.y, src);
    outi.z = __shfl_sync(0xffffffffu, pim.z, src);
    outi.w = __shfl_sync(0xffffffffu, pim.w, src);
}

// ---------------------------------------------------------------------------
// K0: U = expm(-i*dt*H) (degree-4 Taylor, packed f32x2), then a Kogge-Stone
// INCLUSIVE SCAN over the 8 lanes of each chunk (shfl_up, no swaps):
// lane l ends with prefix_l = U_l ... U_0, stored to g_U.
// prefix_7 doubles as the chunk product consumed by k_scan. No smem/barriers.
__global__ void __launch_bounds__(128, 6) k_expm(const float* __restrict__ hr_g,
                                                 const float* __restrict__ hi_g) {
    int tid = threadIdx.x;
    int idx = blockIdx.x * 128 + tid;
    int el = tid & 7;

    const float4* hr4 = reinterpret_cast<const float4*>(hr_g) + (size_t)idx * 4;
    const float4* hi4 = reinterpret_cast<const float4*>(hi_g) + (size_t)idx * 4;

    // A = dt*hi - i*dt*hr
    PRow A[4];
    const u64p pdt = psplat(DT), pndt = psplat(-DT);
#pragma unroll
    for (int i = 0; i < 4; ++i) {
        float4 r = hr4[i], m = hi4[i];
        A[i].r01 = pmul(pdt,  pk2(m.x, m.y));
        A[i].r23 = pmul(pdt,  pk2(m.z, m.w));
        A[i].i01 = pmul(pndt, pk2(r.x, r.y));
        A[i].i23 = pmul(pndt, pk2(r.z, r.w));
    }

    // B = A^2 (row-wise)
    PRow B[4];
#pragma unroll
    for (int i = 0; i < 4; ++i) B[i] = prow_mm(A[i], A);

    // E = A + M·B, M = I/2 + A/6 + B/24 built row-by-row (A,B commute)
    const u64p c6 = psplat(1.0f / 6.0f), c24 = psplat(1.0f / 24.0f);
#pragma unroll
    for (int i = 0; i < 4; ++i) {
        PRow m;
        m.r01 = pfma(c6, A[i].r01, pmul(c24, B[i].r01));
        m.r23 = pfma(c6, A[i].r23, pmul(c24, B[i].r23));
        m.i01 = pfma(c6, A[i].i01, pmul(c24, B[i].i01));
        m.i23 = pfma(c6, A[i].i23, pmul(c24, B[i].i23));
        if (i == 0) m.r01 = padd(m.r01, pk2(0.5f, 0.0f));
        if (i == 1) m.r01 = padd(m.r01, pk2(0.0f, 0.5f));
        if (i == 2) m.r23 = padd(m.r23, pk2(0.5f, 0.0f));
        if (i == 3) m.r23 = padd(m.r23, pk2(0.0f, 0.5f));
        float e0, e1, e2, e3, f0, f1, f2, f3;
        upk2(m.r01, e0, e1); upk2(m.r23, e2, e3);
        upk2(m.i01, f0, f1); upk2(m.i23, f2, f3);
        caccum(e0, f0, B[0], A[i]);
        caccum(e1, f1, B[1], A[i]);
        caccum(e2, f2, B[2], A[i]);
        caccum(e3, f3, B[3], A[i]);
    }
    A[0].r01 = padd(A[0].r01, pk2(1.0f, 0.0f));
    A[1].r01 = padd(A[1].r01, pk2(0.0f, 1.0f));
    A[2].r23 = padd(A[2].r23, pk2(1.0f, 0.0f));
    A[3].r23 = padd(A[3].r23, pk2(0.0f, 1.0f));

    // ---- Kogge-Stone inclusive scan across the 8-lane chunk group.
    // Round d: lanes el>=d do A = A(newer, left) * Q(from lane el-d, right).
#pragma unroll
    for (int d = 1; d < 8; d <<= 1) {
        PRow Q[4];
#pragma unroll
        for (int i = 0; i < 4; ++i) {
            Q[i].r01 = __shfl_up_sync(0xffffffffu, A[i].r01, d, 8);
            Q[i].r23 = __shfl_up_sync(0xffffffffu, A[i].r23, d, 8);
            Q[i].i01 = __shfl_up_sync(0xffffffffu, A[i].i01, d, 8);
            Q[i].i23 = __shfl_up_sync(0xffffffffu, A[i].i23, d, 8);
        }
        if (el >= d) {
#pragma unroll
            for (int i = 0; i < 4; ++i) A[i] = prow_mm(A[i], Q);
        }
    }

    // store prefix to g_U (planar: re[16] then im[16]) — coalesced
    {
        float4* Up = g_U + (size_t)idx * 8;
#pragma unroll
        for (int i = 0; i < 4; ++i) {
            float x0, x1, x2, x3;
            upk2(A[i].r01, x0, x1); upk2(A[i].r23, x2, x3);
            Up[i] = make_float4(x0, x1, x2, x3);
        }
#pragma unroll
        for (int i = 0; i < 4; ++i) {
            float x0, x1, x2, x3;
            upk2(A[i].i01, x0, x1); upk2(A[i].i23, x2, x3);
            Up[4 + i] = make_float4(x0, x1, x2, x3);
        }
    }
}

// ---------------------------------------------------------------------------
// K2: TWO-LEVEL row-parallel scan per batch. 1024 threads = 256 chunks x 4 rows.
// Chunk products are read from g_U at t = e*8+7 (prefix_7 of each chunk).
#define TOFF 288   // T_B offset (T matrices stride 9 quads; 32*9=288 per buffer)

__global__ void __launch_bounds__(1024) k_scan(const float* __restrict__ s0r_g,
                                               const float* __restrict__ s0i_g) {
    __shared__ float4 sh[CC * 12];   // 48KB; quads [0,576) double as T_A/T_B
    int b = blockIdx.x;
    int tid = threadIdx.x;
    int e = tid >> 2, i = tid & 3;
    int lane = tid & 31;
    int el = lane >> 2;              // local chunk within warp (0..7)
    int g = e >> 3;                  // group (= warp id, 0..31)

    const float4* Pg = g_U + ((size_t)b * TT + (size_t)e * LL + (LL - 1)) * 8;
    float4 pr = Pg[i], pim = Pg[4 + i];

    // ---- L1: warp-local KS over 8 (rows fetched via shfl)
#pragma unroll
    for (int d = 1; d < 8; d <<= 1) {
        int srcb = ((el >= d) ? (el - d) : 0) << 2;
        float4 l0r, l0i, l1r, l1i, l2r, l2i, l3r, l3i;
        shfl_row(pr, pim, srcb + 0, l0r, l0i);
        shfl_row(pr, pim, srcb + 1, l1r, l1i);
        shfl_row(pr, pim, srcb + 2, l2r, l2i);
        shfl_row(pr, pim, srcb + 3, l3r, l3i);
        if (el >= d) {
            float4 nr = make_float4(0, 0, 0, 0), ni = make_float4(0, 0, 0, 0);
            cax4(pr.x, pim.x, l0r, l0i, nr, ni);
            cax4(pr.y, pim.y, l1r, l1i, nr, ni);
            cax4(pr.z, pim.z, l2r, l2i, nr, ni);
            cax4(pr.w, pim.w, l3r, l3i, nr, ni);
            pr = nr; pim = ni;
        }
    }

    // ---- publish group totals (el==7) into T_A (stride 9 quads per matrix)
    if (el == 7) {
        sh[g * 9 + i] = pr;
        sh[g * 9 + 4 + i] = pim;
    }
    __syncthreads();

    // ---- L2: KS over 32 totals, 128 threads, 5 rounds, double-buffered
    if (tid < 128) {
        int g2 = tid >> 2, i2 = tid & 3;
        int rb = 0;
#pragma unroll
        for (int d = 1; d < 32; d <<= 1) {
            const float4* src = sh + rb;
            float4* dst = sh + (TOFF - rb);
            float4 qr = src[g2 * 9 + i2], qi = src[g2 * 9 + 4 + i2];
            if (g2 >= d) {
                const float4* nb = src + (size_t)(g2 - d) * 9;
                float4 nr = make_float4(0, 0, 0, 0), ni = make_float4(0, 0, 0, 0);
                cax4(qr.x, qi.x, nb[0], nb[4], nr, ni);
                cax4(qr.y, qi.y, nb[1], nb[5], nr, ni);
                cax4(qr.z, qi.z, nb[2], nb[6], nr, ni);
                cax4(qr.w, qi.w, nb[3], nb[7], nr, ni);
                qr = nr; qi = ni;
            }
            dst[g2 * 9 + i2] = qr;
            dst[g2 * 9 + 4 + i2] = qi;
            asm volatile("bar.sync 1, 128;" ::: "memory");
            rb = TOFF - rb;
        }
    }
    __syncthreads();
    // G (inclusive group prefixes) now at sh + TOFF

    // ---- inclusive prefix: Q_e * G_{g-1}
    if (g > 0) {
        const float4* nb = sh + TOFF + (size_t)(g - 1) * 9;
        float4 nr = make_float4(0, 0, 0, 0), ni = make_float4(0, 0, 0, 0);
        cax4(pr.x, pim.x, nb[0], nb[4], nr, ni);
        cax4(pr.y, pim.y, nb[1], nb[5], nr, ni);
        cax4(pr.z, pim.z, nb[2], nb[6], nr, ni);
        cax4(pr.w, pim.w, nb[3], nb[7], nr, ni);
        pr = nr; pim = ni;
    }
    __syncthreads();   // everyone done reading T before overwriting sh below

    // ---- publish inclusive rows (XOR-swizzled layout)
    int es = e & 7;
    {
        float4* me = sh + e * 12;
        me[i ^ es] = pr;
        me[(4 + i) ^ es] = pim;
    }
    __syncthreads();

    // ---- V_e = Prefix_{e-1} * S0  (V_0 = S0)
    const float4* r4 = reinterpret_cast<const float4*>(s0r_g) + (size_t)b * 4;
    const float4* i4 = reinterpret_cast<const float4*>(s0i_g) + (size_t)b * 4;
    float4 s0r0 = r4[0], s0r1 = r4[1], s0r2 = r4[2], s0r3 = r4[3];
    float4 s0i0 = i4[0], s0i1 = i4[1], s0i2 = i4[2], s0i3 = i4[3];

    float4 vr, vi;
    if (e == 0) {
        vr = (i == 0) ? s0r0 : (i == 1) ? s0r1 : (i == 2) ? s0r2 : s0r3;
        vi = (i == 0) ? s0i0 : (i == 1) ? s0i1 : (i == 2) ? s0i2 : s0i3;
    } else {
        int ens = (e - 1) & 7;
        const float4* nb = sh + (e - 1) * 12;
        float4 qr = nb[i ^ ens];
        float4 qi = nb[(4 + i) ^ ens];
        vr = make_float4(0, 0, 0, 0); vi = make_float4(0, 0, 0, 0);
        cax4(qr.x, qi.x, s0r0, s0i0, vr, vi);
        cax4(qr.y, qi.y, s0r1, s0i1, vr, vi);
        cax4(qr.z, qi.z, s0r2, s0i2, vr, vi);
        cax4(qr.w, qi.w, s0r3, s0i3, vr, vi);
    }
    float4* Sg = g_S + ((size_t)b * CC + e) * 8;
    Sg[i] = vr;
    Sg[4 + i] = vi;
}

// ---------------------------------------------------------------------------
// K3: apply via prefixes — 8 INDEPENDENT products per thread, no smem/sync.
// Thread = (chunk gidx, row i), batch-major: warp = 8 consecutive b, same c.
// S_{c*8+l} = prefix_l * V_c ; row i needs only prefix row i and full V.
__global__ void __launch_bounds__(128) k_apply(float* __restrict__ out) {
    int tid = threadIdx.x;
    int cl = tid >> 2, i = tid & 3;
    int gidx = blockIdx.x * 32 + cl;         // b-fast ordering
    int b = gidx & (BB - 1);
    int c = gidx >> 7;                       // / BB
    int idx = b * CC + c;

    // full incoming state V (group-broadcast loads, L1-served)
    const float4* Vg = g_S + (size_t)idx * 8;
    float4 v0r = Vg[0], v1r = Vg[1], v2r = Vg[2], v3r = Vg[3];
    float4 v0i = Vg[4], v1i = Vg[5], v2i = Vg[6], v3i = Vg[7];

    const float4* Ug = g_U + ((size_t)b * TT + (size_t)c * LL) * 8;
    const size_t imag_off = (size_t)TT * BB * 16;
    float* ob = out + (((size_t)c * LL) * BB + b) * 16 + i * 4;

#pragma unroll
    for (int l = 0; l < LL; ++l) {
        float4 pr = Ug[l * 8 + i];           // prefix_l row i, real
        float4 pi = Ug[l * 8 + 4 + i];       // imag

        float4 nr = make_float4(0, 0, 0, 0), ni = make_float4(0, 0, 0, 0);
        cax4(pr.x, pi.x, v0r, v0i, nr, ni);
        cax4(pr.y, pi.y, v1r, v1i, nr, ni);
        cax4(pr.z, pi.z, v2r, v2i, nr, ni);
        cax4(pr.w, pi.w, v3r, v3i, nr, ni);

        float* op = ob + (size_t)l * BB * 16;
        __stcs(reinterpret_cast<float4*>(op), nr);
        __stcs(reinterpret_cast<float4*>(op + imag_off), ni);
    }
}

// ---------------------------------------------------------------------------
extern "C" void kernel_launch(void* const* d_in, const int* in_sizes, int n_in,
                              void* d_out, int out_size) {
    const float* h_real = (const float*)d_in[0];
    const float* h_imag = (const float*)d_in[1];
    const float* s_real = (const float*)d_in[2];
    const float* s_imag = (const float*)d_in[3];
    float* out = (float*)d_out;

    k_expm<<<NM / 128, 128>>>(h_real, h_imag);
    k_scan<<<BB, CC * 4>>>(s_real, s_imag);
    k_apply<<<(BB * CC) / 32, 128>>>(out);
}